// round 3
// baseline (speedup 1.0000x reference)
#include <cuda_runtime.h>

// SliceLSTM persistent kernel, round 3.
// B=64, T=512, S=4, DIN=64, H=128, HTOT=512.
// 128 CTAs x 512 threads, all co-resident; global ticket barrier (single-thread
// fence + acquire poll). f32x2 FFMA over COLUMN pairs with broadcast
// activations: b-major staging (no transpose, no bank conflicts), weights read
// directly as packed ulonglong2. x_{t+1} prefetched during phase 3.

#define NCTA 128
#define NTHR 512

// shared layout (floats)
#define OFF_W1 0        // 192 x 16
#define OFF_B1 3072     // 16
#define OFF_W2 3088     // 64 x 128
#define OFF_AX 11280    // 64 x 65  (x slice, b-major, pad 65)
#define OFF_AH 15440    // 64 x 129 (h slice, b-major, pad 129)
#define OFF_A2 23696    // 64 x 65  (P2 activation chunk)
#define SMEM_BYTES 118784   // 116KB: fits 27856 floats, blocks 2 CTAs/SM

__device__ float g_h[64 * 512];            // hidden state [b][c]
__device__ float g_act[4 * 64 * 512];      // stage-1 activated gates [gate][b][c]
__device__ float g_part[NCTA * 64 * 128];  // connector partials [cta][b][c_local]
__device__ unsigned long long g_bar;       // monotonic ticket counter

static __device__ __forceinline__ unsigned long long pk2(float lo, float hi) {
    unsigned long long r;
    asm("mov.b64 %0, {%1, %2};" : "=l"(r) : "f"(lo), "f"(hi));
    return r;
}
static __device__ __forceinline__ void unp2(unsigned long long v, float& lo, float& hi) {
    asm("mov.b64 {%0, %1}, %2;" : "=f"(lo), "=f"(hi) : "l"(v));
}
static __device__ __forceinline__ void fma2(unsigned long long& d,
                                            unsigned long long a, unsigned long long b) {
    asm("fma.rn.f32x2 %0, %1, %2, %0;" : "+l"(d) : "l"(a), "l"(b));
}
static __device__ __forceinline__ float sigf(float x)  { return 1.0f / (1.0f + __expf(-x)); }
static __device__ __forceinline__ float tanhe(float x) {
    float e = __expf(2.0f * x);
    return 1.0f - 2.0f / (e + 1.0f);
}

// Global ticket barrier over all 128 resident CTAs.
// syncthreads first; ONE thread fences (cumulative over CTA stores), adds the
// ticket, and acquire-polls. No per-thread membar, no nanosleep.
static __device__ __forceinline__ void gbar() {
    __syncthreads();
    if (threadIdx.x == 0) {
        __threadfence();
        unsigned long long tk = atomicAdd(&g_bar, 1ULL);
        unsigned long long goal = tk - (tk & (unsigned long long)(NCTA - 1)) + NCTA;
        unsigned long long v;
        do {
            asm volatile("ld.acquire.gpu.u64 %0, [%1];" : "=l"(v) : "l"(&g_bar));
        } while (v < goal);
    }
    __syncthreads();
}

__global__ void __launch_bounds__(NTHR, 1)
slstm_kernel(const float* __restrict__ x,       // (64, 512, 256)
             const float* __restrict__ Ws,      // (4, 64, 512)
             const float* __restrict__ Us,      // (4, 128, 512)
             const float* __restrict__ biases,  // (4, 512)
             const float* __restrict__ Wc,      // (512, 2048)
             const float* __restrict__ bc,      // (2048,)
             float* __restrict__ out)           // hseq | h_t | c_t
{
    extern __shared__ float sm[];
    float* sW1 = sm + OFF_W1;
    float* sB1 = sm + OFF_B1;
    float* sW2 = sm + OFF_W2;
    float* sAx = sm + OFF_AX;
    float* sAh = sm + OFF_AH;
    float* sA2 = sm + OFF_A2;

    const int tid = threadIdx.x;
    const int cta = blockIdx.x;

    // Phase-1 role: slice s1, 16 of the 512 stage-1 gate cols (one gate)
    const int s1    = cta >> 5;
    const int u0    = (cta & 31) * 16;
    const int gate1 = u0 >> 7;
    const int col0  = s1 * 128 + (u0 & 127);

    // Phase-2 role: gate g2, 128-col tile c20, 64-row K-chunk k20
    const int g2  = cta >> 5;
    const int r2  = cta & 31;
    const int c20 = (r2 >> 3) * 128;
    const int k20 = (r2 & 7) * 64;

    // Phase-3 role: one (b,c) per thread for tid<256
    const int p3  = cta * 256 + (tid & 255);
    const int b3  = p3 >> 9;
    const int c3  = p3 & 511;
    const int ct3 = c3 >> 7;
    const int cl3 = c3 & 127;

    // ---- persistent weights into SMEM ----
    for (int i = tid; i < 192 * 16; i += NTHR) {
        int k = i >> 4, c = i & 15;
        sW1[i] = (k < 64) ? Ws[s1 * (64 * 512) + k * 512 + u0 + c]
                          : Us[s1 * (128 * 512) + (k - 64) * 512 + u0 + c];
    }
    if (tid < 16) sB1[tid] = biases[s1 * 512 + u0 + tid];
    for (int i = tid; i < 64 * 128; i += NTHR) {
        int k = i >> 7, c = i & 127;
        sW2[k * 128 + c] = Wc[(k20 + k) * 2048 + g2 * 512 + c20 + c];
    }

    float bci = 0.f, bcf = 0.f, bcg = 0.f, bco = 0.f;
    float creg = 0.f, hlast = 0.f;
    if (tid < 256) {
        bci = bc[c3]; bcf = bc[512 + c3]; bcg = bc[1024 + c3]; bco = bc[1536 + c3];
        g_h[p3] = 0.0f;     // h0 = 0
    }
    // stage x for t=0 (b-major, conflict-free)
    for (int i = tid; i < 4096; i += NTHR) {
        int b = i >> 6, k = i & 63;
        sAx[b * 65 + k] = __ldg(&x[b * (512 * 256) + s1 * 64 + k]);
    }
    gbar();

    for (int t = 0; t < 512; ++t) {
        // ============ Phase 1: stage-1 block-diagonal GEMM ============
        for (int i = tid; i < 8192; i += NTHR) {
            int b = i >> 7, k = i & 127;
            sAh[b * 129 + k] = __ldcg(&g_h[b * 512 + s1 * 128 + k]);
        }
        __syncthreads();
        if (tid < 256) {
            const int b1  = tid >> 2;     // batch
            const int cg1 = tid & 3;      // 4-col group
            const float* ax  = sAx + b1 * 65;
            const float* ah  = sAh + b1 * 129;
            const float* wp  = sW1 + cg1 * 4;
            unsigned long long acc0 = 0ULL, acc1 = 0ULL;
            #pragma unroll 4
            for (int k = 0; k < 64; ++k) {
                const ulonglong2 w = *reinterpret_cast<const ulonglong2*>(wp + k * 16);
                const float a = ax[k];
                const unsigned long long ap = pk2(a, a);
                fma2(acc0, ap, w.x);
                fma2(acc1, ap, w.y);
            }
            #pragma unroll 4
            for (int k = 0; k < 128; ++k) {
                const ulonglong2 w = *reinterpret_cast<const ulonglong2*>(wp + (64 + k) * 16);
                const float a = ah[k];
                const unsigned long long ap = pk2(a, a);
                fma2(acc0, ap, w.x);
                fma2(acc1, ap, w.y);
            }
            float v0, v1, v2, v3;
            unp2(acc0, v0, v1);
            unp2(acc1, v2, v3);
            v0 += sB1[cg1 * 4 + 0];
            v1 += sB1[cg1 * 4 + 1];
            v2 += sB1[cg1 * 4 + 2];
            v3 += sB1[cg1 * 4 + 3];
            if (gate1 == 2) { v0 = tanhe(v0); v1 = tanhe(v1); v2 = tanhe(v2); v3 = tanhe(v3); }
            else           { v0 = sigf(v0);  v1 = sigf(v1);  v2 = sigf(v2);  v3 = sigf(v3);  }
            __stcg(reinterpret_cast<float4*>(
                       &g_act[gate1 * 32768 + b1 * 512 + col0 + cg1 * 4]),
                   make_float4(v0, v1, v2, v3));
        }
        gbar();

        // ============ Phase 2: connector GEMM, K-split partials ============
        for (int i = tid; i < 4096; i += NTHR) {
            int b = i >> 6, k = i & 63;
            sA2[b * 65 + k] = __ldcg(&g_act[g2 * 32768 + b * 512 + k20 + k]);
        }
        __syncthreads();
        {
            const int b2 = tid >> 3;      // batch
            const int cg = tid & 7;       // chunk group: owns chunks cg, cg+8, cg+16, cg+24
            unsigned long long acc[8];
            #pragma unroll
            for (int j = 0; j < 8; ++j) acc[j] = 0ULL;
            const float* a2 = sA2 + b2 * 65;
            const float* wb = sW2 + cg * 4;
            #pragma unroll 2
            for (int k = 0; k < 64; ++k) {
                const float a = a2[k];
                const unsigned long long ap = pk2(a, a);
                const float* wr = wb + k * 128;
                const ulonglong2 wA = *reinterpret_cast<const ulonglong2*>(wr);
                const ulonglong2 wB = *reinterpret_cast<const ulonglong2*>(wr + 32);
                const ulonglong2 wC = *reinterpret_cast<const ulonglong2*>(wr + 64);
                const ulonglong2 wD = *reinterpret_cast<const ulonglong2*>(wr + 96);
                fma2(acc[0], ap, wA.x); fma2(acc[1], ap, wA.y);
                fma2(acc[2], ap, wB.x); fma2(acc[3], ap, wB.y);
                fma2(acc[4], ap, wC.x); fma2(acc[5], ap, wC.y);
                fma2(acc[6], ap, wD.x); fma2(acc[7], ap, wD.y);
            }
            float* pp = g_part + cta * 8192 + b2 * 128;
            #pragma unroll
            for (int j = 0; j < 4; ++j) {
                float q0, q1, q2, q3;
                unp2(acc[2 * j],     q0, q1);
                unp2(acc[2 * j + 1], q2, q3);
                __stcg(reinterpret_cast<float4*>(pp + 4 * (cg + 8 * j)),
                       make_float4(q0, q1, q2, q3));
            }
        }
        gbar();

        // ============ Phase 3: reduce + cell update (warps 0-7),
        //              x prefetch for t+1 (warps 8-15) ============
        if (tid < 256) {
            float a0 = 0.f, a1 = 0.f, ag = 0.f, a3 = 0.f;
            const float* gp = g_part + b3 * 128 + cl3;
            #pragma unroll
            for (int kc = 0; kc < 8; ++kc) {
                a0 += __ldcg(gp + (0 * 32 + ct3 * 8 + kc) * 8192);
                a1 += __ldcg(gp + (1 * 32 + ct3 * 8 + kc) * 8192);
                ag += __ldcg(gp + (2 * 32 + ct3 * 8 + kc) * 8192);
                a3 += __ldcg(gp + (3 * 32 + ct3 * 8 + kc) * 8192);
            }
            const float iv = sigf(a0 + bci);
            const float fv = sigf(a1 + bcf);
            const float gv = tanhe(ag + bcg);
            const float ov = sigf(a3 + bco);
            creg = fv * creg + iv * gv;
            const float hn = ov * tanhe(creg);
            hlast = hn;
            __stcg(&g_h[p3], hn);
            out[b3 * (512 * 512) + t * 512 + c3] = hn;
        } else if (t + 1 < 512) {
            for (int i = tid - 256; i < 4096; i += 256) {
                int b = i >> 6, k = i & 63;
                sAx[b * 65 + k] = __ldg(&x[b * (512 * 256) + (t + 1) * 256 + s1 * 64 + k]);
            }
        }
        gbar();
    }

    if (tid < 256) {
        out[16777216 + p3]         = hlast;
        out[16777216 + 32768 + p3] = creg;
    }
}

extern "C" void kernel_launch(void* const* d_in, const int* in_sizes, int n_in,
                              void* d_out, int out_size) {
    const float* x      = (const float*)d_in[0];
    const float* Ws     = (const float*)d_in[1];
    const float* Us     = (const float*)d_in[2];
    const float* biases = (const float*)d_in[3];
    const float* Wc     = (const float*)d_in[4];
    const float* bc     = (const float*)d_in[5];
    float* out = (float*)d_out;
    (void)in_sizes; (void)n_in; (void)out_size;

    cudaFuncSetAttribute(slstm_kernel, cudaFuncAttributeMaxDynamicSharedMemorySize,
                         SMEM_BYTES);
    slstm_kernel<<<NCTA, NTHR, SMEM_BYTES>>>(x, Ws, Us, biases, Wc, bc, out);
}

// round 5
// speedup vs baseline: 1.3391x; 1.3391x over previous
#include <cuda_runtime.h>

// SliceLSTM persistent kernel, round 5 (R4 design + alignment fix).
// B=64, T=512, S=4, DIN=64, H=128, HTOT=512.
// 128 CTAs x 256 threads. Register-blocked FFMA2 GEMMs (P2: 4b x 16c per
// thread), coalesced partial gather in P3, release-atom/acquire-poll barrier.
// SMEM staging uses odd strides (conflict-free) with SCALAR stores.

#define NCTA 128
#define NTHR 256

// shared layout (float offsets)
#define OFF_W1 0        // 192 x 16
#define OFF_B1 3072     // 16
#define OFF_W2 3088     // 64 x 128
#define OFF_A1 11280    // [b 0..63][k 0..191], LD1=193  (k<64: x, k>=64: h)
#define LD1    193
#define OFF_A2 23632    // [b 0..63][k 0..63], LD2=65
#define LD2    65
#define OFF_SC 27792    // scratch: 512 u64 (P1 k-split reduce)
#define SMEM_BYTES 118784

__device__ float g_h[64 * 512];            // hidden state [b][c]
__device__ float g_act[4 * 64 * 512];      // stage-1 activated gates [gate][b][c]
__device__ float g_part[NCTA * 64 * 128];  // connector partials [cta][b][cl]
__device__ unsigned long long g_bar;       // monotonic ticket counter

static __device__ __forceinline__ unsigned long long pk2(float v) {
    unsigned long long r;
    asm("mov.b64 %0, {%1, %1};" : "=l"(r) : "f"(v));
    return r;
}
static __device__ __forceinline__ void unp2(unsigned long long v, float& lo, float& hi) {
    asm("mov.b64 {%0, %1}, %2;" : "=f"(lo), "=f"(hi) : "l"(v));
}
static __device__ __forceinline__ void fma2(unsigned long long& d,
                                            unsigned long long a, unsigned long long b) {
    asm("fma.rn.f32x2 %0, %1, %2, %0;" : "+l"(d) : "l"(a), "l"(b));
}
static __device__ __forceinline__ float sigf(float x)  { return 1.0f / (1.0f + __expf(-x)); }
static __device__ __forceinline__ float tanhe(float x) {
    float e = __expf(2.0f * x);
    return 1.0f - 2.0f / (e + 1.0f);
}

// global barrier: syncthreads; tid0 does release-atom ticket + acquire poll.
static __device__ __forceinline__ void gbar() {
    __syncthreads();
    if (threadIdx.x == 0) {
        unsigned long long tk;
        asm volatile("atom.add.release.gpu.u64 %0, [%1], 1;"
                     : "=l"(tk) : "l"(&g_bar));
        unsigned long long goal = tk - (tk & (unsigned long long)(NCTA - 1)) + NCTA;
        unsigned long long v;
        do {
            asm volatile("ld.acquire.gpu.u64 %0, [%1];" : "=l"(v) : "l"(&g_bar));
        } while (v < goal);
    }
    __syncthreads();
}

__global__ void __launch_bounds__(NTHR, 1)
slstm_kernel(const float* __restrict__ x,       // (64, 512, 256)
             const float* __restrict__ Ws,      // (4, 64, 512)
             const float* __restrict__ Us,      // (4, 128, 512)
             const float* __restrict__ biases,  // (4, 512)
             const float* __restrict__ Wc,      // (512, 2048)
             const float* __restrict__ bc,      // (2048,)
             float* __restrict__ out)           // hseq | h_t | c_t
{
    extern __shared__ float sm[];
    float* sW1 = sm + OFF_W1;
    float* sB1 = sm + OFF_B1;
    float* sW2 = sm + OFF_W2;
    float* sA1 = sm + OFF_A1;
    float* sA2 = sm + OFF_A2;
    unsigned long long* sSc = reinterpret_cast<unsigned long long*>(sm + OFF_SC);

    const int tid = threadIdx.x;
    const int cta = blockIdx.x;

    // P1 role: slice s1, 16 stage-1 cols at u0 (single gate)
    const int s1    = cta >> 5;
    const int u0    = (cta & 31) * 16;
    const int gate1 = u0 >> 7;
    const int col0  = s1 * 128 + (u0 & 127);
    // P1 compute (tid<128): bg:0..31 (2-batch groups), cg:0..1 (8 cols), ks:0..1
    const int p1bg = tid & 31;
    const int p1cg = (tid >> 5) & 1;
    const int p1ks = (tid >> 6) & 1;

    // P2 role: gate g2, col-tile c20, K-chunk k20
    const int g2  = cta >> 5;
    const int r2  = cta & 31;
    const int c20 = (r2 >> 3) * 128;
    const int k20 = (r2 & 7) * 64;
    // P2 compute (tid<128): bg = tid&15 (4-batch groups), cg = tid>>4 (16 cols)
    const int p2bg = tid & 15;
    const int p2cg = tid >> 4;

    // P3 role (tid<64): slot owns (b3, cols c3..c3+3)
    const int slot = cta * 64 + tid;
    const int b3 = slot >> 7;
    const int c3 = (slot & 127) * 4;
    const int ct3 = c3 >> 7;
    const int cl3 = c3 & 127;

    // ---- persistent weights ----
    for (int i = tid; i < 192 * 16; i += NTHR) {
        int k = i >> 4, c = i & 15;
        sW1[i] = (k < 64) ? Ws[s1 * (64 * 512) + k * 512 + u0 + c]
                          : Us[s1 * (128 * 512) + (k - 64) * 512 + u0 + c];
    }
    if (tid < 16) sB1[tid] = biases[s1 * 512 + u0 + tid];
    for (int i = tid; i < 64 * 128; i += NTHR) {
        int k = i >> 7, c = i & 127;
        sW2[k * 128 + c] = Wc[(k20 + k) * 2048 + g2 * 512 + c20 + c];
    }

    // P3 biases + state
    float4 bi = {0,0,0,0}, bf = {0,0,0,0}, bg4 = {0,0,0,0}, bo = {0,0,0,0};
    float4 creg = {0,0,0,0}, hlast = {0,0,0,0};
    if (tid < 64) {
        bi  = *reinterpret_cast<const float4*>(&bc[c3]);
        bf  = *reinterpret_cast<const float4*>(&bc[512 + c3]);
        bg4 = *reinterpret_cast<const float4*>(&bc[1024 + c3]);
        bo  = *reinterpret_cast<const float4*>(&bc[1536 + c3]);
        __stcg(reinterpret_cast<float4*>(&g_h[b3 * 512 + c3]), creg);  // h0 = 0
    }
    // stage x(t=0) into sA1 rows, cols 0..63 (vector global load, scalar STS)
    for (int i = tid; i < 256; i += NTHR) {
        int b = i & 63, q = i >> 6;
        const float4* src = reinterpret_cast<const float4*>(
            &x[b * (512 * 256) + s1 * 64 + q * 16]);
        float* dst = &sA1[b * LD1 + q * 16];
        #pragma unroll
        for (int j = 0; j < 4; ++j) {
            float4 v = __ldg(src + j);
            dst[j * 4 + 0] = v.x; dst[j * 4 + 1] = v.y;
            dst[j * 4 + 2] = v.z; dst[j * 4 + 3] = v.w;
        }
    }
    gbar();

    for (int t = 0; t < 512; ++t) {
        // ========== Phase 1: stage h, block-diag GEMM ==========
        for (int i = tid; i < 256; i += NTHR) {   // 8192 floats: (b, quarter)
            int b = i & 63, q = i >> 6;
            const float4* src = reinterpret_cast<const float4*>(
                &g_h[b * 512 + s1 * 128 + q * 32]);
            float* dst = &sA1[b * LD1 + 64 + q * 32];
            #pragma unroll
            for (int j = 0; j < 8; ++j) {
                float4 v = __ldcg(src + j);
                dst[j * 4 + 0] = v.x; dst[j * 4 + 1] = v.y;
                dst[j * 4 + 2] = v.z; dst[j * 4 + 3] = v.w;
            }
        }
        __syncthreads();
        unsigned long long acc1[2][4];
        if (tid < 128) {
            const int b0 = p1bg * 2;
            const float* a0p = sA1 + (b0 + 0) * LD1;
            const float* a1p = sA1 + (b0 + 1) * LD1;
            const float* wp  = sW1 + p1cg * 8;
            #pragma unroll
            for (int i = 0; i < 2; ++i)
                #pragma unroll
                for (int j = 0; j < 4; ++j) acc1[i][j] = 0ULL;
            const int kbeg = p1ks * 96;
            #pragma unroll 4
            for (int k = kbeg; k < kbeg + 96; ++k) {
                const ulonglong2 wA = *reinterpret_cast<const ulonglong2*>(wp + k * 16);
                const ulonglong2 wB = *reinterpret_cast<const ulonglong2*>(wp + k * 16 + 4);
                const unsigned long long a0 = pk2(a0p[k]);
                const unsigned long long a1 = pk2(a1p[k]);
                fma2(acc1[0][0], a0, wA.x); fma2(acc1[0][1], a0, wA.y);
                fma2(acc1[0][2], a0, wB.x); fma2(acc1[0][3], a0, wB.y);
                fma2(acc1[1][0], a1, wA.x); fma2(acc1[1][1], a1, wA.y);
                fma2(acc1[1][2], a1, wB.x); fma2(acc1[1][3], a1, wB.y);
            }
            if (p1ks == 1) {   // publish upper-half partials
                const int th = tid - 64;
                #pragma unroll
                for (int i = 0; i < 2; ++i)
                    #pragma unroll
                    for (int j = 0; j < 4; ++j)
                        sSc[(i * 4 + j) * 64 + th] = acc1[i][j];
            }
        }
        __syncthreads();
        if (tid < 64) {        // p1ks==0 threads reduce + activate + store
            const int b0 = p1bg * 2;
            #pragma unroll
            for (int i = 0; i < 2; ++i) {
                float v[8];
                #pragma unroll
                for (int j = 0; j < 4; ++j) {
                    float lo, hi, plo, phi;
                    unp2(acc1[i][j], lo, hi);
                    unp2(sSc[(i * 4 + j) * 64 + tid], plo, phi);
                    v[2 * j]     = lo + plo + sB1[p1cg * 8 + 2 * j];
                    v[2 * j + 1] = hi + phi + sB1[p1cg * 8 + 2 * j + 1];
                }
                if (gate1 == 2) {
                    #pragma unroll
                    for (int j = 0; j < 8; ++j) v[j] = tanhe(v[j]);
                } else {
                    #pragma unroll
                    for (int j = 0; j < 8; ++j) v[j] = sigf(v[j]);
                }
                float* dst = &g_act[gate1 * 32768 + (b0 + i) * 512 + col0 + p1cg * 8];
                __stcg(reinterpret_cast<float4*>(dst),
                       make_float4(v[0], v[1], v[2], v[3]));
                __stcg(reinterpret_cast<float4*>(dst + 4),
                       make_float4(v[4], v[5], v[6], v[7]));
            }
        }
        gbar();

        // ========== Phase 2: connector GEMM (K-chunk partials) ==========
        for (int i = tid; i < 256; i += NTHR) {   // 4096 floats
            int b = i & 63, q = i >> 6;
            const float4* src = reinterpret_cast<const float4*>(
                &g_act[g2 * 32768 + b * 512 + k20 + q * 16]);
            float* dst = &sA2[b * LD2 + q * 16];
            #pragma unroll
            for (int j = 0; j < 4; ++j) {
                float4 v = __ldcg(src + j);
                dst[j * 4 + 0] = v.x; dst[j * 4 + 1] = v.y;
                dst[j * 4 + 2] = v.z; dst[j * 4 + 3] = v.w;
            }
        }
        __syncthreads();
        if (tid < 128) {
            const int b0 = p2bg * 4;
            unsigned long long acc[4][8];
            #pragma unroll
            for (int i = 0; i < 4; ++i)
                #pragma unroll
                for (int j = 0; j < 8; ++j) acc[i][j] = 0ULL;
            const float* wbase = sW2 + p2cg * 16;
            #pragma unroll 4
            for (int k = 0; k < 64; ++k) {
                const float* wr = wbase + k * 128;
                const ulonglong2 wA = *reinterpret_cast<const ulonglong2*>(wr);
                const ulonglong2 wB = *reinterpret_cast<const ulonglong2*>(wr + 4);
                const ulonglong2 wC = *reinterpret_cast<const ulonglong2*>(wr + 8);
                const ulonglong2 wD = *reinterpret_cast<const ulonglong2*>(wr + 12);
                #pragma unroll
                for (int i = 0; i < 4; ++i) {
                    const unsigned long long a = pk2(sA2[(b0 + i) * LD2 + k]);
                    fma2(acc[i][0], a, wA.x); fma2(acc[i][1], a, wA.y);
                    fma2(acc[i][2], a, wB.x); fma2(acc[i][3], a, wB.y);
                    fma2(acc[i][4], a, wC.x); fma2(acc[i][5], a, wC.y);
                    fma2(acc[i][6], a, wD.x); fma2(acc[i][7], a, wD.y);
                }
            }
            float* pp = g_part + cta * 8192 + p2cg * 16;
            #pragma unroll
            for (int i = 0; i < 4; ++i) {
                float q0,q1,q2,q3,q4,q5,q6,q7,q8,q9,qa,qb,qc,qd,qe,qf;
                unp2(acc[i][0], q0, q1); unp2(acc[i][1], q2, q3);
                unp2(acc[i][2], q4, q5); unp2(acc[i][3], q6, q7);
                unp2(acc[i][4], q8, q9); unp2(acc[i][5], qa, qb);
                unp2(acc[i][6], qc, qd); unp2(acc[i][7], qe, qf);
                float4* d = reinterpret_cast<float4*>(pp + (b0 + i) * 128);
                __stcg(d + 0, make_float4(q0, q1, q2, q3));
                __stcg(d + 1, make_float4(q4, q5, q6, q7));
                __stcg(d + 2, make_float4(q8, q9, qa, qb));
                __stcg(d + 3, make_float4(qc, qd, qe, qf));
            }
        }
        gbar();

        // ========== Phase 3: coalesced gather + cell update; x prefetch ==========
        if (tid < 64) {
            float4 ai = {0,0,0,0}, af = {0,0,0,0}, ag = {0,0,0,0}, ao = {0,0,0,0};
            const float4* gp = reinterpret_cast<const float4*>(
                g_part + b3 * 128 + cl3);
            #pragma unroll
            for (int kc = 0; kc < 8; ++kc) {
                float4 v;
                v = __ldcg(gp + (0 * 32 + ct3 * 8 + kc) * 2048);
                ai.x += v.x; ai.y += v.y; ai.z += v.z; ai.w += v.w;
                v = __ldcg(gp + (1 * 32 + ct3 * 8 + kc) * 2048);
                af.x += v.x; af.y += v.y; af.z += v.z; af.w += v.w;
                v = __ldcg(gp + (2 * 32 + ct3 * 8 + kc) * 2048);
                ag.x += v.x; ag.y += v.y; ag.z += v.z; ag.w += v.w;
                v = __ldcg(gp + (3 * 32 + ct3 * 8 + kc) * 2048);
                ao.x += v.x; ao.y += v.y; ao.z += v.z; ao.w += v.w;
            }
            float4 hn;
            {
                float iv = sigf(ai.x + bi.x), fv = sigf(af.x + bf.x);
                float gv = tanhe(ag.x + bg4.x), ov = sigf(ao.x + bo.x);
                creg.x = fv * creg.x + iv * gv; hn.x = ov * tanhe(creg.x);
                iv = sigf(ai.y + bi.y); fv = sigf(af.y + bf.y);
                gv = tanhe(ag.y + bg4.y); ov = sigf(ao.y + bo.y);
                creg.y = fv * creg.y + iv * gv; hn.y = ov * tanhe(creg.y);
                iv = sigf(ai.z + bi.z); fv = sigf(af.z + bf.z);
                gv = tanhe(ag.z + bg4.z); ov = sigf(ao.z + bo.z);
                creg.z = fv * creg.z + iv * gv; hn.z = ov * tanhe(creg.z);
                iv = sigf(ai.w + bi.w); fv = sigf(af.w + bf.w);
                gv = tanhe(ag.w + bg4.w); ov = sigf(ao.w + bo.w);
                creg.w = fv * creg.w + iv * gv; hn.w = ov * tanhe(creg.w);
            }
            hlast = hn;
            __stcg(reinterpret_cast<float4*>(&g_h[b3 * 512 + c3]), hn);
            *reinterpret_cast<float4*>(&out[b3 * (512 * 512) + t * 512 + c3]) = hn;
        } else if (t + 1 < 512) {
            for (int i = tid - 64; i < 256; i += 192) {
                int b = i & 63, q = i >> 6;
                const float4* src = reinterpret_cast<const float4*>(
                    &x[b * (512 * 256) + (t + 1) * 256 + s1 * 64 + q * 16]);
                float* dst = &sA1[b * LD1 + q * 16];
                #pragma unroll
                for (int j = 0; j < 4; ++j) {
                    float4 v = __ldg(src + j);
                    dst[j * 4 + 0] = v.x; dst[j * 4 + 1] = v.y;
                    dst[j * 4 + 2] = v.z; dst[j * 4 + 3] = v.w;
                }
            }
        }
        gbar();
    }

    if (tid < 64) {
        *reinterpret_cast<float4*>(&out[16777216 + b3 * 512 + c3]) = hlast;
        *reinterpret_cast<float4*>(&out[16777216 + 32768 + b3 * 512 + c3]) = creg;
    }
}

extern "C" void kernel_launch(void* const* d_in, const int* in_sizes, int n_in,
                              void* d_out, int out_size) {
    const float* x      = (const float*)d_in[0];
    const float* Ws     = (const float*)d_in[1];
    const float* Us     = (const float*)d_in[2];
    const float* biases = (const float*)d_in[3];
    const float* Wc     = (const float*)d_in[4];
    const float* bc     = (const float*)d_in[5];
    float* out = (float*)d_out;
    (void)in_sizes; (void)n_in; (void)out_size;

    cudaFuncSetAttribute(slstm_kernel, cudaFuncAttributeMaxDynamicSharedMemorySize,
                         SMEM_BYTES);
    slstm_kernel<<<NCTA, NTHR, SMEM_BYTES>>>(x, Ws, Us, biases, Wc, bc, out);
}